// round 12
// baseline (speedup 1.0000x reference)
#include <cuda_runtime.h>
#include <cuda_bf16.h>
#include <math.h>
#include <stdint.h>

// Fixed problem shapes
#define NMAX   50000
#define EMAX   800000
#define FMAX   512
#define GCNT   512
#define FPOUT  2048

// Scratch (device globals: no allocation allowed)
__device__ float g_h [(size_t)NMAX * FMAX];  // hh = (x@W)*dis[row]
__device__ float g_x [(size_t)NMAX * FMAX];  // activation ping
__device__ float g_x2[(size_t)NMAX * FMAX];  // activation pong
__device__ float g_dis[NMAX];
__device__ float g_gate[NMAX];
__device__ float g_pool[GCNT * 1024];
__device__ int   g_cnt[NMAX];
__device__ int   g_rowptr[NMAX + 1];
__device__ int   g_fill[NMAX];
__device__ int   g_esrc[EMAX];
__device__ int   g_bsum[256];
__device__ int   g_start[GCNT];
__device__ int   g_end[GCNT];

__device__ __forceinline__ float to_tf32(float x) {
    uint32_t u;
    asm("cvt.rna.tf32.f32 %0, %1;" : "=r"(u) : "f"(x));
    return __uint_as_float(u);
}

__device__ __forceinline__ void mma_tf32(float* c, const uint32_t* a,
                                         uint32_t b0, uint32_t b1) {
    asm volatile(
        "mma.sync.aligned.m16n8k8.row.col.f32.tf32.tf32.f32 "
        "{%0,%1,%2,%3}, {%4,%5,%6,%7}, {%8,%9}, {%0,%1,%2,%3};"
        : "+f"(c[0]), "+f"(c[1]), "+f"(c[2]), "+f"(c[3])
        : "r"(a[0]), "r"(a[1]), "r"(a[2]), "r"(a[3]), "r"(b0), "r"(b1));
}

// ===========================================================================
// GEMM via mma.sync tf32, split precision (hi+lo), CTA 128x128, K-chunk 16,
// double-buffered smem with register staging.
//   bias == null:  C[row] = (A@B)[row] * dis[row]        (node layers, C=hh)
//   bias != null:  C[row] = relu((A@B)[row] + bias[col]) (head)
// 8 warps: warp tile 32(M) x 64(N) = 2 x 8 m16n8k8 atoms, 3 MMAs per atom.
// Requires Nout % 128 == 0, K % 16 == 0.
// ===========================================================================
#define CHK   16
#define PITCH 132
#define STG_F (CHK * PITCH)                 // floats per array-stage (2112)
#define STG_B (STG_F * 4)                   // bytes (8448)
#define OFF_AH(s) ((s) * 4 * STG_B + 0 * STG_B)
#define OFF_AL(s) ((s) * 4 * STG_B + 1 * STG_B)
#define OFF_BH(s) ((s) * 4 * STG_B + 2 * STG_B)
#define OFF_BL(s) ((s) * 4 * STG_B + 3 * STG_B)
#define GEMM_SMEM (2 * 4 * STG_B)           // 67584 B

__global__ void __launch_bounds__(256, 2) gemm_mma_k(
    const float* __restrict__ A, const float* __restrict__ B,
    float* __restrict__ C, int M, int Nout, int K,
    const float* __restrict__ bias)
{
    extern __shared__ char smem[];

    const int tid  = threadIdx.x;
    const int lane = tid & 31;
    const int wid  = tid >> 5;
    const int bm = blockIdx.y * 128;
    const int bn = blockIdx.x * 128;
    const int wm = (wid & 3) * 32;   // warp M offset
    const int wn = (wid >> 2) * 64;  // warp N offset
    const int q = lane >> 2;         // 0..7
    const int s = lane & 3;          // 0..3

    // global-load mapping
    const int a_row = tid >> 1;            // 0..127
    const int a_cb  = (tid & 1) * 8;       // 0 or 8
    const int b_k   = tid >> 4;            // 0..15
    const int b_n   = (tid & 15) * 8;      // 0..120

    const int grow = bm + a_row;
    const int nchunk = K / CHK;

    float acc[2][8][4];
#pragma unroll
    for (int i = 0; i < 2; i++)
#pragma unroll
        for (int j = 0; j < 8; j++)
#pragma unroll
            for (int v = 0; v < 4; v++) acc[i][j][v] = 0.f;

    // ---- convert+store helpers (to stage st) ----
    auto store_chunk = [&](int st, const float4* av, const float4* bv) {
        float* AH = (float*)(smem + OFF_AH(st));
        float* AL = (float*)(smem + OFF_AL(st));
        float* BH = (float*)(smem + OFF_BH(st));
        float* BL = (float*)(smem + OFF_BL(st));
#pragma unroll
        for (int h = 0; h < 2; h++) {
            const int c = a_cb + h * 4;
            float4 v = av[h];
            float hx = to_tf32(v.x), hy = to_tf32(v.y);
            float hz = to_tf32(v.z), hw = to_tf32(v.w);
            AH[(c + 0) * PITCH + a_row] = hx; AL[(c + 0) * PITCH + a_row] = to_tf32(v.x - hx);
            AH[(c + 1) * PITCH + a_row] = hy; AL[(c + 1) * PITCH + a_row] = to_tf32(v.y - hy);
            AH[(c + 2) * PITCH + a_row] = hz; AL[(c + 2) * PITCH + a_row] = to_tf32(v.z - hz);
            AH[(c + 3) * PITCH + a_row] = hw; AL[(c + 3) * PITCH + a_row] = to_tf32(v.w - hw);
        }
#pragma unroll
        for (int h = 0; h < 2; h++) {
            const int n = b_n + h * 4;
            float4 v = bv[h];
            float4 h4, l4;
            h4.x = to_tf32(v.x); l4.x = to_tf32(v.x - h4.x);
            h4.y = to_tf32(v.y); l4.y = to_tf32(v.y - h4.y);
            h4.z = to_tf32(v.z); l4.z = to_tf32(v.z - h4.z);
            h4.w = to_tf32(v.w); l4.w = to_tf32(v.w - h4.w);
            *(float4*)&BH[b_k * PITCH + n] = h4;
            *(float4*)&BL[b_k * PITCH + n] = l4;
        }
    };
    auto load_chunk = [&](int k0, float4* av, float4* bv) {
#pragma unroll
        for (int h = 0; h < 2; h++) {
            av[h] = make_float4(0.f, 0.f, 0.f, 0.f);
            if (grow < M)
                av[h] = *(const float4*)(A + (size_t)grow * K + k0 + a_cb + h * 4);
            bv[h] = *(const float4*)(B + (size_t)(k0 + b_k) * Nout + bn + b_n + h * 4);
        }
    };

    // preload chunk 0
    {
        float4 av[2], bv[2];
        load_chunk(0, av, bv);
        store_chunk(0, av, bv);
    }
    __syncthreads();

    for (int ch = 0; ch < nchunk; ch++) {
        const int buf = ch & 1;
        const bool more = (ch + 1 < nchunk);
        float4 av[2], bv[2];
        if (more) load_chunk((ch + 1) * CHK, av, bv);

        const float* AH = (const float*)(smem + OFF_AH(buf));
        const float* AL = (const float*)(smem + OFF_AL(buf));
        const float* BH = (const float*)(smem + OFF_BH(buf));
        const float* BL = (const float*)(smem + OFF_BL(buf));

#pragma unroll
        for (int k8 = 0; k8 < CHK / 8; k8++) {
            const int kr0 = k8 * 8 + s;
            const int kr1 = kr0 + 4;
            uint32_t ah[2][4], al[2][4];
#pragma unroll
            for (int am = 0; am < 2; am++) {
                const int r0 = wm + am * 16 + q;
                ah[am][0] = __float_as_uint(AH[kr0 * PITCH + r0]);
                ah[am][1] = __float_as_uint(AH[kr0 * PITCH + r0 + 8]);
                ah[am][2] = __float_as_uint(AH[kr1 * PITCH + r0]);
                ah[am][3] = __float_as_uint(AH[kr1 * PITCH + r0 + 8]);
                al[am][0] = __float_as_uint(AL[kr0 * PITCH + r0]);
                al[am][1] = __float_as_uint(AL[kr0 * PITCH + r0 + 8]);
                al[am][2] = __float_as_uint(AL[kr1 * PITCH + r0]);
                al[am][3] = __float_as_uint(AL[kr1 * PITCH + r0 + 8]);
            }
#pragma unroll
            for (int an = 0; an < 8; an++) {
                const int n0 = wn + an * 8 + q;
                const uint32_t bh0 = __float_as_uint(BH[kr0 * PITCH + n0]);
                const uint32_t bh1 = __float_as_uint(BH[kr1 * PITCH + n0]);
                const uint32_t bl0 = __float_as_uint(BL[kr0 * PITCH + n0]);
                const uint32_t bl1 = __float_as_uint(BL[kr1 * PITCH + n0]);
#pragma unroll
                for (int am = 0; am < 2; am++) {
                    mma_tf32(acc[am][an], ah[am], bh0, bh1);
                    mma_tf32(acc[am][an], al[am], bh0, bh1);
                    mma_tf32(acc[am][an], ah[am], bl0, bl1);
                }
            }
        }

        if (more) {
            store_chunk(buf ^ 1, av, bv);
            __syncthreads();
        }
    }

    // ---- epilogue ----
    const bool hashead = (bias != nullptr);
#pragma unroll
    for (int am = 0; am < 2; am++) {
        const int row0 = bm + wm + am * 16 + q;
        const int row1 = row0 + 8;
        const float d0 = (!hashead && row0 < M) ? g_dis[row0] : 0.f;
        const float d1 = (!hashead && row1 < M) ? g_dis[row1] : 0.f;
#pragma unroll
        for (int an = 0; an < 8; an++) {
            const int col = bn + wn + an * 8 + s * 2;
            if (hashead) {
                const float bx = bias[col], by = bias[col + 1];
                if (row0 < M) {
                    float2 o = make_float2(fmaxf(acc[am][an][0] + bx, 0.f),
                                           fmaxf(acc[am][an][1] + by, 0.f));
                    *(float2*)(C + (size_t)row0 * Nout + col) = o;
                }
                if (row1 < M) {
                    float2 o = make_float2(fmaxf(acc[am][an][2] + bx, 0.f),
                                           fmaxf(acc[am][an][3] + by, 0.f));
                    *(float2*)(C + (size_t)row1 * Nout + col) = o;
                }
            } else {
                if (row0 < M) {
                    float2 o = make_float2(acc[am][an][0] * d0, acc[am][an][1] * d0);
                    *(float2*)(C + (size_t)row0 * Nout + col) = o;
                }
                if (row1 < M) {
                    float2 o = make_float2(acc[am][an][2] * d1, acc[am][an][3] * d1);
                    *(float2*)(C + (size_t)row1 * Nout + col) = o;
                }
            }
        }
    }
}

// ---------------------------------------------------------------------------
// CSR build: histogram -> 3-pass parallel scan -> cursor scatter
// ---------------------------------------------------------------------------
__global__ void cnt_zero_k(int n) {
    int i = blockIdx.x * blockDim.x + threadIdx.x;
    if (i < n) g_cnt[i] = 0;
}
__global__ void hist_k(const int* __restrict__ dst, int e) {
    int i = blockIdx.x * blockDim.x + threadIdx.x;
    if (i < e) atomicAdd(&g_cnt[dst[i]], 1);
}
__global__ void dis_k(int n) {
    int i = blockIdx.x * blockDim.x + threadIdx.x;
    if (i < n) g_dis[i] = rsqrtf((float)(g_cnt[i] + 1));  // +1 self-loop
}
__global__ void scan1_k(int n) {
    __shared__ int sh[256];
    int i = blockIdx.x * 256 + threadIdx.x;
    sh[threadIdx.x] = (i < n) ? g_cnt[i] : 0;
    __syncthreads();
    for (int o = 128; o > 0; o >>= 1) {
        if (threadIdx.x < o) sh[threadIdx.x] += sh[threadIdx.x + o];
        __syncthreads();
    }
    if (threadIdx.x == 0) g_bsum[blockIdx.x] = sh[0];
}
__global__ void scan2_k(int nb, int n) {
    __shared__ int sh[256];
    int t = threadIdx.x;
    int v = (t < nb) ? g_bsum[t] : 0;
    sh[t] = v; __syncthreads();
    for (int o = 1; o < 256; o <<= 1) {
        int u = (t >= o) ? sh[t - o] : 0;
        __syncthreads();
        sh[t] += u;
        __syncthreads();
    }
    if (t < nb) g_bsum[t] = sh[t] - v;  // exclusive
    if (t == 255) g_rowptr[n] = sh[255];
}
__global__ void scan3_k(int n) {
    __shared__ int sh[256];
    int t = threadIdx.x;
    int i = blockIdx.x * 256 + t;
    int v = (i < n) ? g_cnt[i] : 0;
    sh[t] = v; __syncthreads();
    for (int o = 1; o < 256; o <<= 1) {
        int u = (t >= o) ? sh[t - o] : 0;
        __syncthreads();
        sh[t] += u;
        __syncthreads();
    }
    if (i < n) {
        int off = g_bsum[blockIdx.x] + sh[t] - v;
        g_rowptr[i] = off;
        g_fill[i] = off;
    }
}
__global__ void scatter_k(const int* __restrict__ src, const int* __restrict__ dst,
                          int e) {
    int i = blockIdx.x * blockDim.x + threadIdx.x;
    if (i >= e) return;
    int pos = atomicAdd(&g_fill[dst[i]], 1);
    g_esrc[pos] = src[i];
}

// ---------------------------------------------------------------------------
// Pull-aggregation (warp per node):
//   x_out[d] = relu(dis[d] * (hh[d] + sum_{s in in(d)} hh[s]) + bias)
// Optional fused gate: g_gate[d] = sigmoid(dot(x_out[d], pw)+pb)
// ---------------------------------------------------------------------------
template <int NF4>
__global__ void __launch_bounds__(256) agg_csr_k(
    const float* __restrict__ hh, float* __restrict__ xo,
    const float* __restrict__ bias, int n,
    const float* __restrict__ pw, const float* __restrict__ pb, int dogate)
{
    int w = (blockIdx.x * blockDim.x + threadIdx.x) >> 5;
    if (w >= n) return;
    const int lane = threadIdx.x & 31;
    const int f = NF4 * 128;

    float4 acc[NF4];
    const float4* hrow = (const float4*)(hh + (size_t)w * f);
#pragma unroll
    for (int j = 0; j < NF4; j++) acc[j] = hrow[j * 32 + lane];  // self term

    const int beg = g_rowptr[w], end = g_rowptr[w + 1];
    for (int e = beg; e < end; e++) {
        int s = g_esrc[e];
        const float4* hs = (const float4*)(hh + (size_t)s * f);
#pragma unroll
        for (int j = 0; j < NF4; j++) {
            float4 v = hs[j * 32 + lane];
            acc[j].x += v.x; acc[j].y += v.y; acc[j].z += v.z; acc[j].w += v.w;
        }
    }

    const float nd = g_dis[w];
    float4* xrow = (float4*)(xo + (size_t)w * f);
    float gdot = 0.f;
#pragma unroll
    for (int j = 0; j < NF4; j++) {
        float4 b = ((const float4*)bias)[j * 32 + lane];
        float4 o;
        o.x = fmaxf(fmaf(acc[j].x, nd, b.x), 0.f);
        o.y = fmaxf(fmaf(acc[j].y, nd, b.y), 0.f);
        o.z = fmaxf(fmaf(acc[j].z, nd, b.z), 0.f);
        o.w = fmaxf(fmaf(acc[j].w, nd, b.w), 0.f);
        xrow[j * 32 + lane] = o;
        if (dogate) {
            float4 p = ((const float4*)pw)[j * 32 + lane];
            gdot += o.x * p.x + o.y * p.y + o.z * p.z + o.w * p.w;
        }
    }
    if (dogate) {
#pragma unroll
        for (int off = 16; off > 0; off >>= 1)
            gdot += __shfl_xor_sync(0xffffffffu, gdot, off);
        if (lane == 0) g_gate[w] = 1.f / (1.f + expf(-(gdot + pb[0])));
    }
}

// ---------------------------------------------------------------------------
// Segment bounds + pooling
// ---------------------------------------------------------------------------
__global__ void seg_init_k(int n) {
    int g = blockIdx.x * blockDim.x + threadIdx.x;
    if (g < GCNT) { g_start[g] = n; g_end[g] = 0; }
}
__global__ void seg_bounds_k(const int* __restrict__ batch, int n) {
    int i = blockIdx.x * blockDim.x + threadIdx.x;
    if (i >= n) return;
    int g = batch[i];
    atomicMin(&g_start[g], i);
    atomicMax(&g_end[g], i + 1);
}
__global__ void __launch_bounds__(512) pool_k(const float* __restrict__ x) {
    int g = blockIdx.x;
    int s = g_start[g], e = g_end[g];
    int f = threadIdx.x;
    float sum = 0.f, mx = 0.f;
    for (int i = s; i < e; i++) {
        float v = x[(size_t)i * 512 + f];
        sum += v * g_gate[i];
        mx = fmaxf(mx, v);
    }
    g_pool[g * 1024 + f] = sum;
    g_pool[g * 1024 + 512 + f] = mx;  // post-ReLU x >= 0 == empty-segment fill
}

// ---------------------------------------------------------------------------
// Launch
// ---------------------------------------------------------------------------
extern "C" void kernel_launch(void* const* d_in, const int* in_sizes, int n_in,
                              void* d_out, int out_size) {
    const float* xin   = (const float*)d_in[0];
    const int*   ei    = (const int*)d_in[1];
    const int*   batch = (const int*)d_in[2];
    const float* W1 = (const float*)d_in[3];
    const float* b1 = (const float*)d_in[4];
    const float* W2 = (const float*)d_in[5];
    const float* b2 = (const float*)d_in[6];
    const float* W3 = (const float*)d_in[7];
    const float* b3 = (const float*)d_in[8];
    const float* pw = (const float*)d_in[9];
    const float* pb = (const float*)d_in[10];
    const float* Wo = (const float*)d_in[11];
    const float* bo = (const float*)d_in[12];
    float* out = (float*)d_out;

    const int N = in_sizes[0] / 256;
    const int E = in_sizes[1] / 2;
    const int* src = ei;
    const int* dst = ei + E;

    float *p_h, *p_xa, *p_xb, *p_pool;
    cudaGetSymbolAddress((void**)&p_h,  g_h);
    cudaGetSymbolAddress((void**)&p_xa, g_x);
    cudaGetSymbolAddress((void**)&p_xb, g_x2);
    cudaGetSymbolAddress((void**)&p_pool, g_pool);

    cudaFuncSetAttribute(gemm_mma_k,
                         cudaFuncAttributeMaxDynamicSharedMemorySize, GEMM_SMEM);

    // CSR build + normalization
    const int nb = (N + 255) / 256;
    cnt_zero_k<<<nb, 256>>>(N);
    hist_k<<<(E + 255) / 256, 256>>>(dst, E);
    dis_k<<<nb, 256>>>(N);
    scan1_k<<<nb, 256>>>(N);
    scan2_k<<<1, 256>>>(nb, N);
    scan3_k<<<nb, 256>>>(N);
    scatter_k<<<(E + 255) / 256, 256>>>(src, dst, E);

    // --- GCN layers ---
    struct { const float *W, *b; int fin, fout; } L[3] = {
        {W1, b1, 256, 256}, {W2, b2, 256, 256}, {W3, b3, 256, 512}};
    const float* cur = xin;
    float* act[2] = {p_xa, p_xb};
    float* x_out = nullptr;
    for (int l = 0; l < 3; l++) {
        int fin = L[l].fin, fout = L[l].fout;
        x_out = act[l & 1];
        dim3 grid(fout / 128, (N + 127) / 128);
        gemm_mma_k<<<grid, 256, GEMM_SMEM>>>(cur, L[l].W, p_h, N, fout, fin,
                                             nullptr);
        int aggblocks = (N * 32 + 255) / 256;
        if (fout == 256)
            agg_csr_k<2><<<aggblocks, 256>>>(p_h, x_out, L[l].b, N, pw, pb, 0);
        else
            agg_csr_k<4><<<aggblocks, 256>>>(p_h, x_out, L[l].b, N, pw, pb,
                                             (l == 2) ? 1 : 0);
        cur = x_out;
    }

    // --- Pooling ---
    seg_init_k<<<(GCNT + 255) / 256, 256>>>(N);
    seg_bounds_k<<<nb, 256>>>(batch, N);
    pool_k<<<GCNT, 512>>>(x_out);

    // --- Head: relu(pool @ Wo + bo) via MMA ---
    dim3 hgrid(FPOUT / 128, (GCNT + 127) / 128);
    gemm_mma_k<<<hgrid, 256, GEMM_SMEM>>>(p_pool, Wo, out, GCNT, FPOUT, 1024,
                                          bo);
}

// round 14
// speedup vs baseline: 1.2215x; 1.2215x over previous
#include <cuda_runtime.h>
#include <cuda_bf16.h>
#include <math.h>
#include <stdint.h>

// Fixed problem shapes
#define NMAX   50000
#define EMAX   800000
#define FMAX   512
#define GCNT   512
#define FPOUT  2048
#define WTOT   2359296   // W1 65536 + W2 65536 + W3 131072 + Wo 2097152

// Scratch (device globals: no allocation allowed)
__device__ float g_h [(size_t)NMAX * FMAX];  // hh = (x@W)*dis[row]
__device__ float g_x [(size_t)NMAX * FMAX];  // activation ping
__device__ float g_x2[(size_t)NMAX * FMAX];  // activation pong
__device__ float g_wh[WTOT];                 // weight hi (tf32)
__device__ float g_wl[WTOT];                 // weight lo (tf32)
__device__ float g_dis[NMAX];
__device__ float g_gate[NMAX];
__device__ float g_pool[GCNT * 1024];
__device__ int   g_cnt[NMAX];
__device__ int   g_rowptr[NMAX + 1];
__device__ int   g_fill[NMAX];
__device__ int   g_esrc[EMAX];
__device__ int   g_bsum[256];
__device__ int   g_start[GCNT];
__device__ int   g_end[GCNT];

__device__ __forceinline__ float to_tf32(float x) {
    uint32_t u;
    asm("cvt.rna.tf32.f32 %0, %1;" : "=r"(u) : "f"(x));
    return __uint_as_float(u);
}
__device__ __forceinline__ uint32_t smem_u32(const void* p) {
    uint32_t a;
    asm("{ .reg .u64 t; cvta.to.shared.u64 t, %1; cvt.u32.u64 %0, t; }"
        : "=r"(a) : "l"(p));
    return a;
}
__device__ __forceinline__ void cp16(uint32_t dst, const void* src, int srcbytes) {
    asm volatile("cp.async.cg.shared.global [%0], [%1], 16, %2;"
                 :: "r"(dst), "l"(src), "r"(srcbytes) : "memory");
}
#define CP_COMMIT() asm volatile("cp.async.commit_group;" ::: "memory")
#define CP_WAIT1()  asm volatile("cp.async.wait_group 1;" ::: "memory")
#define CP_WAIT0()  asm volatile("cp.async.wait_group 0;" ::: "memory")

__device__ __forceinline__ void mma_tf32(float* c, const uint32_t* a,
                                         uint32_t b0, uint32_t b1) {
    asm volatile(
        "mma.sync.aligned.m16n8k8.row.col.f32.tf32.tf32.f32 "
        "{%0,%1,%2,%3}, {%4,%5,%6,%7}, {%8,%9}, {%0,%1,%2,%3};"
        : "+f"(c[0]), "+f"(c[1]), "+f"(c[2]), "+f"(c[3])
        : "r"(a[0]), "r"(a[1]), "r"(a[2]), "r"(a[3]), "r"(b0), "r"(b1));
}

// ===========================================================================
// GEMM via mma.sync tf32 split-precision, cp.async 2-stage pipeline.
//   bias == null:  C[row] = (A@B)[row] * dis[row]         (node, C = hh)
//   bias != null:  C[row] = relu((A@B)[row] + bias[col])  (head)
// B is pre-split (WH=hi, WL=lo, tf32 values stored as f32).
// A raw fp32 in smem; split hi/lo at fragment load.
// CTA 128x128, K-chunk 16, 8 warps, warp tile 32x64, 3 MMAs per atom.
// ===========================================================================
#define CHK 16
#define PA  20     // A smem pitch (floats): conflict-free fragment loads
#define PB  136    // B smem pitch (floats): conflict-free fragment loads
#define SZ_A  (128 * PA * 4)             // 10240 B
#define SZ_B  (CHK * PB * 4)             // 8704 B
#define STAGE (SZ_A + 2 * SZ_B)          // 27648 B
#define OFF_A(st)  ((st) * STAGE)
#define OFF_BH(st) ((st) * STAGE + SZ_A)
#define OFF_BL(st) ((st) * STAGE + SZ_A + SZ_B)
#define GEMM_SMEM (2 * STAGE)            // 55296 B

__global__ void __launch_bounds__(256, 2) gemm_mma_k(
    const float* __restrict__ A, const float* __restrict__ WH,
    const float* __restrict__ WL, float* __restrict__ C,
    int M, int Nout, int K, const float* __restrict__ bias)
{
    extern __shared__ char smem[];
    const uint32_t sb = smem_u32(smem);

    const int tid  = threadIdx.x;
    const int lane = tid & 31;
    const int wid  = tid >> 5;
    const int bm = blockIdx.y * 128;
    const int bn = blockIdx.x * 128;
    const int wm = (wid & 3) * 32;
    const int wn = (wid >> 2) * 64;
    const int q = lane >> 2;
    const int s = lane & 3;

    const int nchunk = K / CHK;

    float acc[2][8][4];
#pragma unroll
    for (int i = 0; i < 2; i++)
#pragma unroll
        for (int j = 0; j < 8; j++)
#pragma unroll
            for (int v = 0; v < 4; v++) acc[i][j][v] = 0.f;

    // prefetch: A 512 x 16B chunks, BH 512, BL 512; 256 threads x 2 each
    auto prefetch = [&](int ch) {
        const int st = ch & 1;
        const int k0 = ch * CHK;
#pragma unroll
        for (int r = 0; r < 2; r++) {
            const int c = tid + r * 256;
            // A: row = c>>2 (0..127), 16B-chunk = c&3
            {
                const int row = c >> 2, off = c & 3;
                const int grow = bm + row;
                cp16(sb + OFF_A(st) + row * (PA * 4) + off * 16,
                     A + (size_t)grow * K + k0 + off * 4,
                     (grow < M) ? 16 : 0);
            }
            // B: krow = c>>5 (0..15), 16B-chunk = c&31
            {
                const int kr = c >> 5, off = c & 31;
                const size_t gsrc = (size_t)(k0 + kr) * Nout + bn + off * 4;
                cp16(sb + OFF_BH(st) + kr * (PB * 4) + off * 16, WH + gsrc, 16);
                cp16(sb + OFF_BL(st) + kr * (PB * 4) + off * 16, WL + gsrc, 16);
            }
        }
        CP_COMMIT();
    };

    prefetch(0);
    prefetch(1);

    for (int ch = 0; ch < nchunk; ch++) {
        const int buf = ch & 1;
        if (ch + 1 < nchunk) { CP_WAIT1(); } else { CP_WAIT0(); }
        __syncthreads();

        const float* As = (const float*)(smem + OFF_A(buf));
        const float* BH = (const float*)(smem + OFF_BH(buf));
        const float* BL = (const float*)(smem + OFF_BL(buf));

#pragma unroll
        for (int k8 = 0; k8 < CHK / 8; k8++) {
            const int kr0 = k8 * 8 + s;
            const int kr1 = kr0 + 4;
            uint32_t ah[2][4], al[2][4];
#pragma unroll
            for (int am = 0; am < 2; am++) {
                const int r0 = wm + am * 16 + q;
                const float v0 = As[r0 * PA + kr0];
                const float v1 = As[(r0 + 8) * PA + kr0];
                const float v2 = As[r0 * PA + kr1];
                const float v3 = As[(r0 + 8) * PA + kr1];
                float h;
                h = to_tf32(v0); ah[am][0] = __float_as_uint(h); al[am][0] = __float_as_uint(to_tf32(v0 - h));
                h = to_tf32(v1); ah[am][1] = __float_as_uint(h); al[am][1] = __float_as_uint(to_tf32(v1 - h));
                h = to_tf32(v2); ah[am][2] = __float_as_uint(h); al[am][2] = __float_as_uint(to_tf32(v2 - h));
                h = to_tf32(v3); ah[am][3] = __float_as_uint(h); al[am][3] = __float_as_uint(to_tf32(v3 - h));
            }
#pragma unroll
            for (int an = 0; an < 8; an++) {
                const int n0 = wn + an * 8 + q;
                const uint32_t bh0 = __float_as_uint(BH[kr0 * PB + n0]);
                const uint32_t bh1 = __float_as_uint(BH[kr1 * PB + n0]);
                const uint32_t bl0 = __float_as_uint(BL[kr0 * PB + n0]);
                const uint32_t bl1 = __float_as_uint(BL[kr1 * PB + n0]);
#pragma unroll
                for (int am = 0; am < 2; am++) {
                    mma_tf32(acc[am][an], ah[am], bh0, bh1);
                    mma_tf32(acc[am][an], al[am], bh0, bh1);
                    mma_tf32(acc[am][an], ah[am], bl0, bl1);
                }
            }
        }
        __syncthreads();
        if (ch + 2 < nchunk) prefetch(ch + 2);
    }

    // ---- epilogue ----
    const bool hashead = (bias != nullptr);
#pragma unroll
    for (int am = 0; am < 2; am++) {
        const int row0 = bm + wm + am * 16 + q;
        const int row1 = row0 + 8;
        const float d0 = (!hashead && row0 < M) ? g_dis[row0] : 0.f;
        const float d1 = (!hashead && row1 < M) ? g_dis[row1] : 0.f;
#pragma unroll
        for (int an = 0; an < 8; an++) {
            const int col = bn + wn + an * 8 + s * 2;
            if (hashead) {
                const float bx = bias[col], by = bias[col + 1];
                if (row0 < M) {
                    float2 o = make_float2(fmaxf(acc[am][an][0] + bx, 0.f),
                                           fmaxf(acc[am][an][1] + by, 0.f));
                    *(float2*)(C + (size_t)row0 * Nout + col) = o;
                }
                if (row1 < M) {
                    float2 o = make_float2(fmaxf(acc[am][an][2] + bx, 0.f),
                                           fmaxf(acc[am][an][3] + by, 0.f));
                    *(float2*)(C + (size_t)row1 * Nout + col) = o;
                }
            } else {
                if (row0 < M) {
                    float2 o = make_float2(acc[am][an][0] * d0, acc[am][an][1] * d0);
                    *(float2*)(C + (size_t)row0 * Nout + col) = o;
                }
                if (row1 < M) {
                    float2 o = make_float2(acc[am][an][2] * d1, acc[am][an][3] * d1);
                    *(float2*)(C + (size_t)row1 * Nout + col) = o;
                }
            }
        }
    }
}

// ---------------------------------------------------------------------------
// Weight pre-split: WH = tf32(W), WL = tf32(W - WH)
// ---------------------------------------------------------------------------
__global__ void wsplit_k(const float* __restrict__ W, int n, int dstoff) {
    int i = blockIdx.x * blockDim.x + threadIdx.x;
    if (i >= n) return;
    float w = W[i];
    float h = to_tf32(w);
    g_wh[dstoff + i] = h;
    g_wl[dstoff + i] = to_tf32(w - h);
}

// ---------------------------------------------------------------------------
// CSR build: histogram -> 3-pass parallel scan -> cursor scatter
// ---------------------------------------------------------------------------
__global__ void cnt_zero_k(int n) {
    int i = blockIdx.x * blockDim.x + threadIdx.x;
    if (i < n) g_cnt[i] = 0;
}
__global__ void hist_k(const int* __restrict__ dst, int e) {
    int i = blockIdx.x * blockDim.x + threadIdx.x;
    if (i < e) atomicAdd(&g_cnt[dst[i]], 1);
}
__global__ void dis_k(int n) {
    int i = blockIdx.x * blockDim.x + threadIdx.x;
    if (i < n) g_dis[i] = rsqrtf((float)(g_cnt[i] + 1));  // +1 self-loop
}
__global__ void scan1_k(int n) {
    __shared__ int sh[256];
    int i = blockIdx.x * 256 + threadIdx.x;
    sh[threadIdx.x] = (i < n) ? g_cnt[i] : 0;
    __syncthreads();
    for (int o = 128; o > 0; o >>= 1) {
        if (threadIdx.x < o) sh[threadIdx.x] += sh[threadIdx.x + o];
        __syncthreads();
    }
    if (threadIdx.x == 0) g_bsum[blockIdx.x] = sh[0];
}
__global__ void scan2_k(int nb, int n) {
    __shared__ int sh[256];
    int t = threadIdx.x;
    int v = (t < nb) ? g_bsum[t] : 0;
    sh[t] = v; __syncthreads();
    for (int o = 1; o < 256; o <<= 1) {
        int u = (t >= o) ? sh[t - o] : 0;
        __syncthreads();
        sh[t] += u;
        __syncthreads();
    }
    if (t < nb) g_bsum[t] = sh[t] - v;  // exclusive
    if (t == 255) g_rowptr[n] = sh[255];
}
__global__ void scan3_k(int n) {
    __shared__ int sh[256];
    int t = threadIdx.x;
    int i = blockIdx.x * 256 + t;
    int v = (i < n) ? g_cnt[i] : 0;
    sh[t] = v; __syncthreads();
    for (int o = 1; o < 256; o <<= 1) {
        int u = (t >= o) ? sh[t - o] : 0;
        __syncthreads();
        sh[t] += u;
        __syncthreads();
    }
    if (i < n) {
        int off = g_bsum[blockIdx.x] + sh[t] - v;
        g_rowptr[i] = off;
        g_fill[i] = off;
    }
}
__global__ void scatter_k(const int* __restrict__ src, const int* __restrict__ dst,
                          int e) {
    int i = blockIdx.x * blockDim.x + threadIdx.x;
    if (i >= e) return;
    int pos = atomicAdd(&g_fill[dst[i]], 1);
    g_esrc[pos] = src[i];
}

// ---------------------------------------------------------------------------
// Pull-aggregation (warp per node):
//   x_out[d] = relu(dis[d] * (hh[d] + sum_{s in in(d)} hh[s]) + bias)
// Optional fused gate: g_gate[d] = sigmoid(dot(x_out[d], pw)+pb)
// ---------------------------------------------------------------------------
template <int NF4>
__global__ void __launch_bounds__(256) agg_csr_k(
    const float* __restrict__ hh, float* __restrict__ xo,
    const float* __restrict__ bias, int n,
    const float* __restrict__ pw, const float* __restrict__ pb, int dogate)
{
    int w = (blockIdx.x * blockDim.x + threadIdx.x) >> 5;
    if (w >= n) return;
    const int lane = threadIdx.x & 31;
    const int f = NF4 * 128;

    float4 acc[NF4];
    const float4* hrow = (const float4*)(hh + (size_t)w * f);
#pragma unroll
    for (int j = 0; j < NF4; j++) acc[j] = hrow[j * 32 + lane];  // self term

    const int beg = g_rowptr[w], end = g_rowptr[w + 1];
    for (int e = beg; e < end; e++) {
        int s = g_esrc[e];
        const float4* hs = (const float4*)(hh + (size_t)s * f);
#pragma unroll
        for (int j = 0; j < NF4; j++) {
            float4 v = hs[j * 32 + lane];
            acc[j].x += v.x; acc[j].y += v.y; acc[j].z += v.z; acc[j].w += v.w;
        }
    }

    const float nd = g_dis[w];
    float4* xrow = (float4*)(xo + (size_t)w * f);
    float gdot = 0.f;
#pragma unroll
    for (int j = 0; j < NF4; j++) {
        float4 b = ((const float4*)bias)[j * 32 + lane];
        float4 o;
        o.x = fmaxf(fmaf(acc[j].x, nd, b.x), 0.f);
        o.y = fmaxf(fmaf(acc[j].y, nd, b.y), 0.f);
        o.z = fmaxf(fmaf(acc[j].z, nd, b.z), 0.f);
        o.w = fmaxf(fmaf(acc[j].w, nd, b.w), 0.f);
        xrow[j * 32 + lane] = o;
        if (dogate) {
            float4 p = ((const float4*)pw)[j * 32 + lane];
            gdot += o.x * p.x + o.y * p.y + o.z * p.z + o.w * p.w;
        }
    }
    if (dogate) {
#pragma unroll
        for (int off = 16; off > 0; off >>= 1)
            gdot += __shfl_xor_sync(0xffffffffu, gdot, off);
        if (lane == 0) g_gate[w] = 1.f / (1.f + expf(-(gdot + pb[0])));
    }
}

// ---------------------------------------------------------------------------
// Segment bounds + pooling
// ---------------------------------------------------------------------------
__global__ void seg_init_k(int n) {
    int g = blockIdx.x * blockDim.x + threadIdx.x;
    if (g < GCNT) { g_start[g] = n; g_end[g] = 0; }
}
__global__ void seg_bounds_k(const int* __restrict__ batch, int n) {
    int i = blockIdx.x * blockDim.x + threadIdx.x;
    if (i >= n) return;
    int g = batch[i];
    atomicMin(&g_start[g], i);
    atomicMax(&g_end[g], i + 1);
}
__global__ void __launch_bounds__(512) pool_k(const float* __restrict__ x) {
    int g = blockIdx.x;
    int s = g_start[g], e = g_end[g];
    int f = threadIdx.x;
    float sum = 0.f, mx = 0.f;
    for (int i = s; i < e; i++) {
        float v = x[(size_t)i * 512 + f];
        sum += v * g_gate[i];
        mx = fmaxf(mx, v);
    }
    g_pool[g * 1024 + f] = sum;
    g_pool[g * 1024 + 512 + f] = mx;  // post-ReLU x >= 0 == empty-segment fill
}

// ---------------------------------------------------------------------------
// Launch
// ---------------------------------------------------------------------------
extern "C" void kernel_launch(void* const* d_in, const int* in_sizes, int n_in,
                              void* d_out, int out_size) {
    const float* xin   = (const float*)d_in[0];
    const int*   ei    = (const int*)d_in[1];
    const int*   batch = (const int*)d_in[2];
    const float* W1 = (const float*)d_in[3];
    const float* b1 = (const float*)d_in[4];
    const float* W2 = (const float*)d_in[5];
    const float* b2 = (const float*)d_in[6];
    const float* W3 = (const float*)d_in[7];
    const float* b3 = (const float*)d_in[8];
    const float* pw = (const float*)d_in[9];
    const float* pb = (const float*)d_in[10];
    const float* Wo = (const float*)d_in[11];
    const float* bo = (const float*)d_in[12];
    float* out = (float*)d_out;

    const int N = in_sizes[0] / 256;
    const int E = in_sizes[1] / 2;
    const int* src = ei;
    const int* dst = ei + E;

    float *p_h, *p_xa, *p_xb, *p_pool, *p_wh, *p_wl;
    cudaGetSymbolAddress((void**)&p_h,  g_h);
    cudaGetSymbolAddress((void**)&p_xa, g_x);
    cudaGetSymbolAddress((void**)&p_xb, g_x2);
    cudaGetSymbolAddress((void**)&p_pool, g_pool);
    cudaGetSymbolAddress((void**)&p_wh, g_wh);
    cudaGetSymbolAddress((void**)&p_wl, g_wl);

    cudaFuncSetAttribute(gemm_mma_k,
                         cudaFuncAttributeMaxDynamicSharedMemorySize, GEMM_SMEM);

    // Weight pre-split (hi/lo tf32)
    const int woff[4] = {0, 65536, 131072, 262144};
    wsplit_k<<<(65536 + 255) / 256, 256>>>(W1, 65536, woff[0]);
    wsplit_k<<<(65536 + 255) / 256, 256>>>(W2, 65536, woff[1]);
    wsplit_k<<<(131072 + 255) / 256, 256>>>(W3, 131072, woff[2]);
    wsplit_k<<<(2097152 + 255) / 256, 256>>>(Wo, 2097152, woff[3]);

    // CSR build + normalization
    const int nb = (N + 255) / 256;
    cnt_zero_k<<<nb, 256>>>(N);
    hist_k<<<(E + 255) / 256, 256>>>(dst, E);
    dis_k<<<nb, 256>>>(N);
    scan1_k<<<nb, 256>>>(N);
    scan2_k<<<1, 256>>>(nb, N);
    scan3_k<<<nb, 256>>>(N);
    scatter_k<<<(E + 255) / 256, 256>>>(src, dst, E);

    // --- GCN layers ---
    struct { int woff; const float* b; int fin, fout; } L[3] = {
        {0, b1, 256, 256}, {65536, b2, 256, 256}, {131072, b3, 256, 512}};
    const float* cur = xin;
    float* act[2] = {p_xa, p_xb};
    float* x_out = nullptr;
    for (int l = 0; l < 3; l++) {
        int fin = L[l].fin, fout = L[l].fout;
        x_out = act[l & 1];
        dim3 grid(fout / 128, (N + 127) / 128);
        gemm_mma_k<<<grid, 256, GEMM_SMEM>>>(cur, p_wh + L[l].woff,
                                             p_wl + L[l].woff, p_h,
                                             N, fout, fin, nullptr);
        int aggblocks = (N * 32 + 255) / 256;
        if (fout == 256)
            agg_csr_k<2><<<aggblocks, 256>>>(p_h, x_out, L[l].b, N, pw, pb, 0);
        else
            agg_csr_k<4><<<aggblocks, 256>>>(p_h, x_out, L[l].b, N, pw, pb,
                                             (l == 2) ? 1 : 0);
        cur = x_out;
    }

    // --- Pooling ---
    seg_init_k<<<(GCNT + 255) / 256, 256>>>(N);
    seg_bounds_k<<<nb, 256>>>(batch, N);
    pool_k<<<GCNT, 512>>>(x_out);

    // --- Head: relu(pool @ Wo + bo) via MMA ---
    dim3 hgrid(FPOUT / 128, (GCNT + 127) / 128);
    gemm_mma_k<<<hgrid, 256, GEMM_SMEM>>>(p_pool, p_wh + 262144, p_wl + 262144,
                                          out, GCNT, FPOUT, 1024, bo);
}

// round 15
// speedup vs baseline: 1.2868x; 1.0534x over previous
#include <cuda_runtime.h>
#include <cuda_bf16.h>
#include <math.h>
#include <stdint.h>

// Fixed problem shapes
#define NMAX   50000
#define EMAX   800000
#define FMAX   512
#define GCNT   512
#define FPOUT  2048
#define WTOT   2359296   // W1 65536 + W2 65536 + W3 131072 + Wo 2097152

// Scratch (device globals: no allocation allowed)
__device__ float g_s [(size_t)NMAX * 256];   // aggregated input (pre-GEMM)
__device__ float g_x [(size_t)NMAX * FMAX];  // activation ping
__device__ float g_x2[(size_t)NMAX * FMAX];  // activation pong
__device__ float g_wh[WTOT];                 // weight hi (tf32)
__device__ float g_wl[WTOT];                 // weight lo (tf32)
__device__ float g_dis[NMAX];
__device__ float g_gate[NMAX];
__device__ float g_pool[GCNT * 1024];
__device__ int   g_cnt[NMAX];
__device__ int   g_rowptr[NMAX + 1];
__device__ int   g_fill[NMAX];
__device__ int   g_esrc[EMAX];
__device__ int   g_bsum[256];
__device__ int   g_start[GCNT];
__device__ int   g_end[GCNT];

__device__ __forceinline__ float to_tf32(float x) {
    uint32_t u;
    asm("cvt.rna.tf32.f32 %0, %1;" : "=r"(u) : "f"(x));
    return __uint_as_float(u);
}
__device__ __forceinline__ uint32_t smem_u32(const void* p) {
    uint32_t a;
    asm("{ .reg .u64 t; cvta.to.shared.u64 t, %1; cvt.u32.u64 %0, t; }"
        : "=r"(a) : "l"(p));
    return a;
}
__device__ __forceinline__ void cp16(uint32_t dst, const void* src, int srcbytes) {
    asm volatile("cp.async.cg.shared.global [%0], [%1], 16, %2;"
                 :: "r"(dst), "l"(src), "r"(srcbytes) : "memory");
}
#define CP_COMMIT() asm volatile("cp.async.commit_group;" ::: "memory")
#define CP_WAIT2()  asm volatile("cp.async.wait_group 2;" ::: "memory")
#define CP_WAIT1()  asm volatile("cp.async.wait_group 1;" ::: "memory")
#define CP_WAIT0()  asm volatile("cp.async.wait_group 0;" ::: "memory")

__device__ __forceinline__ void mma_tf32(float* c, const uint32_t* a,
                                         uint32_t b0, uint32_t b1) {
    asm volatile(
        "mma.sync.aligned.m16n8k8.row.col.f32.tf32.tf32.f32 "
        "{%0,%1,%2,%3}, {%4,%5,%6,%7}, {%8,%9}, {%0,%1,%2,%3};"
        : "+f"(c[0]), "+f"(c[1]), "+f"(c[2]), "+f"(c[3])
        : "r"(a[0]), "r"(a[1]), "r"(a[2]), "r"(a[3]), "r"(b0), "r"(b1));
}

// ===========================================================================
// GEMM via mma.sync tf32 split-precision, cp.async 3-stage pipeline.
//   C[row] = relu((A@B)[row] + bias[col])    (all GEMMs: node layers + head)
// B pre-split (WH hi / WL lo, tf32 values). A raw fp32 in smem, split at
// fragment load. CTA 128x128, K-chunk 16, 8 warps, warp tile 32x64.
// ===========================================================================
#define CHK 16
#define PA  20     // A smem pitch (floats)
#define PB  136    // B smem pitch (floats)
#define SZ_A  (128 * PA * 4)             // 10240 B
#define SZ_B  (CHK * PB * 4)             // 8704 B
#define STAGE (SZ_A + 2 * SZ_B)          // 27648 B
#define NSTG  3
#define OFF_A(st)  ((st) * STAGE)
#define OFF_BH(st) ((st) * STAGE + SZ_A)
#define OFF_BL(st) ((st) * STAGE + SZ_A + SZ_B)
#define GEMM_SMEM (NSTG * STAGE)         // 82944 B

__global__ void __launch_bounds__(256, 2) gemm_mma_k(
    const float* __restrict__ A, const float* __restrict__ WH,
    const float* __restrict__ WL, float* __restrict__ C,
    int M, int Nout, int K, const float* __restrict__ bias)
{
    extern __shared__ char smem[];
    const uint32_t sb = smem_u32(smem);

    const int tid  = threadIdx.x;
    const int lane = tid & 31;
    const int wid  = tid >> 5;
    const int bm = blockIdx.y * 128;
    const int bn = blockIdx.x * 128;
    const int wm = (wid & 3) * 32;
    const int wn = (wid >> 2) * 64;
    const int q = lane >> 2;
    const int s = lane & 3;

    const int nchunk = K / CHK;

    float acc[2][8][4];
#pragma unroll
    for (int i = 0; i < 2; i++)
#pragma unroll
        for (int j = 0; j < 8; j++)
#pragma unroll
            for (int v = 0; v < 4; v++) acc[i][j][v] = 0.f;

    auto prefetch = [&](int ch) {
        const int st = ch % NSTG;
        const int k0 = ch * CHK;
#pragma unroll
        for (int r = 0; r < 2; r++) {
            const int c = tid + r * 256;
            {
                const int row = c >> 2, off = c & 3;
                const int grow = bm + row;
                cp16(sb + OFF_A(st) + row * (PA * 4) + off * 16,
                     A + (size_t)grow * K + k0 + off * 4,
                     (grow < M) ? 16 : 0);
            }
            {
                const int kr = c >> 5, off = c & 31;
                const size_t gsrc = (size_t)(k0 + kr) * Nout + bn + off * 4;
                cp16(sb + OFF_BH(st) + kr * (PB * 4) + off * 16, WH + gsrc, 16);
                cp16(sb + OFF_BL(st) + kr * (PB * 4) + off * 16, WL + gsrc, 16);
            }
        }
        CP_COMMIT();
    };

    prefetch(0); prefetch(1); prefetch(2);

    for (int ch = 0; ch < nchunk; ch++) {
        const int buf = ch % NSTG;
        const int rem = nchunk - ch - 1;
        if (rem >= 2) { CP_WAIT2(); } else if (rem == 1) { CP_WAIT1(); }
        else { CP_WAIT0(); }
        __syncthreads();

        const float* As = (const float*)(smem + OFF_A(buf));
        const float* BH = (const float*)(smem + OFF_BH(buf));
        const float* BL = (const float*)(smem + OFF_BL(buf));

#pragma unroll
        for (int k8 = 0; k8 < CHK / 8; k8++) {
            const int kr0 = k8 * 8 + s;
            const int kr1 = kr0 + 4;
            uint32_t ah[2][4], al[2][4];
#pragma unroll
            for (int am = 0; am < 2; am++) {
                const int r0 = wm + am * 16 + q;
                const float v0 = As[r0 * PA + kr0];
                const float v1 = As[(r0 + 8) * PA + kr0];
                const float v2 = As[r0 * PA + kr1];
                const float v3 = As[(r0 + 8) * PA + kr1];
                float h;
                h = to_tf32(v0); ah[am][0] = __float_as_uint(h); al[am][0] = __float_as_uint(to_tf32(v0 - h));
                h = to_tf32(v1); ah[am][1] = __float_as_uint(h); al[am][1] = __float_as_uint(to_tf32(v1 - h));
                h = to_tf32(v2); ah[am][2] = __float_as_uint(h); al[am][2] = __float_as_uint(to_tf32(v2 - h));
                h = to_tf32(v3); ah[am][3] = __float_as_uint(h); al[am][3] = __float_as_uint(to_tf32(v3 - h));
            }
#pragma unroll
            for (int an = 0; an < 8; an++) {
                const int n0 = wn + an * 8 + q;
                const uint32_t bh0 = __float_as_uint(BH[kr0 * PB + n0]);
                const uint32_t bh1 = __float_as_uint(BH[kr1 * PB + n0]);
                const uint32_t bl0 = __float_as_uint(BL[kr0 * PB + n0]);
                const uint32_t bl1 = __float_as_uint(BL[kr1 * PB + n0]);
#pragma unroll
                for (int am = 0; am < 2; am++) {
                    mma_tf32(acc[am][an], ah[am], bh0, bh1);
                    mma_tf32(acc[am][an], al[am], bh0, bh1);
                    mma_tf32(acc[am][an], ah[am], bl0, bl1);
                }
            }
        }
        __syncthreads();
        if (ch + NSTG < nchunk) prefetch(ch + NSTG);
    }

    // ---- epilogue: C = relu(acc + bias) ----
#pragma unroll
    for (int am = 0; am < 2; am++) {
        const int row0 = bm + wm + am * 16 + q;
        const int row1 = row0 + 8;
#pragma unroll
        for (int an = 0; an < 8; an++) {
            const int col = bn + wn + an * 8 + s * 2;
            const float bx = bias[col], by = bias[col + 1];
            if (row0 < M) {
                float2 o = make_float2(fmaxf(acc[am][an][0] + bx, 0.f),
                                       fmaxf(acc[am][an][1] + by, 0.f));
                *(float2*)(C + (size_t)row0 * Nout + col) = o;
            }
            if (row1 < M) {
                float2 o = make_float2(fmaxf(acc[am][an][2] + bx, 0.f),
                                       fmaxf(acc[am][an][3] + by, 0.f));
                *(float2*)(C + (size_t)row1 * Nout + col) = o;
            }
        }
    }
}

// ---------------------------------------------------------------------------
// Weight pre-split: WH = tf32(W), WL = tf32(W - WH)
// ---------------------------------------------------------------------------
__global__ void wsplit_k(const float* __restrict__ W, int n, int dstoff) {
    int i = blockIdx.x * blockDim.x + threadIdx.x;
    if (i >= n) return;
    float w = W[i];
    float h = to_tf32(w);
    g_wh[dstoff + i] = h;
    g_wl[dstoff + i] = to_tf32(w - h);
}

// ---------------------------------------------------------------------------
// CSR build: histogram -> 3-pass parallel scan -> cursor scatter
// ---------------------------------------------------------------------------
__global__ void cnt_zero_k(int n) {
    int i = blockIdx.x * blockDim.x + threadIdx.x;
    if (i < n) g_cnt[i] = 0;
}
__global__ void hist_k(const int* __restrict__ dst, int e) {
    int i = blockIdx.x * blockDim.x + threadIdx.x;
    if (i < e) atomicAdd(&g_cnt[dst[i]], 1);
}
__global__ void dis_k(int n) {
    int i = blockIdx.x * blockDim.x + threadIdx.x;
    if (i < n) g_dis[i] = rsqrtf((float)(g_cnt[i] + 1));  // +1 self-loop
}
__global__ void scan1_k(int n) {
    __shared__ int sh[256];
    int i = blockIdx.x * 256 + threadIdx.x;
    sh[threadIdx.x] = (i < n) ? g_cnt[i] : 0;
    __syncthreads();
    for (int o = 128; o > 0; o >>= 1) {
        if (threadIdx.x < o) sh[threadIdx.x] += sh[threadIdx.x + o];
        __syncthreads();
    }
    if (threadIdx.x == 0) g_bsum[blockIdx.x] = sh[0];
}
__global__ void scan2_k(int nb, int n) {
    __shared__ int sh[256];
    int t = threadIdx.x;
    int v = (t < nb) ? g_bsum[t] : 0;
    sh[t] = v; __syncthreads();
    for (int o = 1; o < 256; o <<= 1) {
        int u = (t >= o) ? sh[t - o] : 0;
        __syncthreads();
        sh[t] += u;
        __syncthreads();
    }
    if (t < nb) g_bsum[t] = sh[t] - v;  // exclusive
    if (t == 255) g_rowptr[n] = sh[255];
}
__global__ void scan3_k(int n) {
    __shared__ int sh[256];
    int t = threadIdx.x;
    int i = blockIdx.x * 256 + t;
    int v = (i < n) ? g_cnt[i] : 0;
    sh[t] = v; __syncthreads();
    for (int o = 1; o < 256; o <<= 1) {
        int u = (t >= o) ? sh[t - o] : 0;
        __syncthreads();
        sh[t] += u;
        __syncthreads();
    }
    if (i < n) {
        int off = g_bsum[blockIdx.x] + sh[t] - v;
        g_rowptr[i] = off;
        g_fill[i] = off;
    }
}
__global__ void scatter_k(const int* __restrict__ src, const int* __restrict__ dst,
                          int e) {
    int i = blockIdx.x * blockDim.x + threadIdx.x;
    if (i >= e) return;
    int pos = atomicAdd(&g_fill[dst[i]], 1);
    g_esrc[pos] = src[i];
}

// ---------------------------------------------------------------------------
// Pre-GEMM pull-aggregation (warp per node, 256 features fixed):
//   xa[d] = dis[d] * (dis[d]*x[d] + sum_{s in in(d)} dis[s]*x[s])
// ---------------------------------------------------------------------------
__global__ void __launch_bounds__(256) agg_pre_k(
    const float* __restrict__ x, float* __restrict__ xa, int n)
{
    int w = (blockIdx.x * blockDim.x + threadIdx.x) >> 5;
    if (w >= n) return;
    const int lane = threadIdx.x & 31;

    const float dd = g_dis[w];
    float4 acc[2];
    const float4* xr = (const float4*)(x + (size_t)w * 256);
#pragma unroll
    for (int j = 0; j < 2; j++) {
        float4 v = xr[j * 32 + lane];
        acc[j].x = v.x * dd; acc[j].y = v.y * dd;
        acc[j].z = v.z * dd; acc[j].w = v.w * dd;
    }

    const int beg = g_rowptr[w], end = g_rowptr[w + 1];
    for (int e = beg; e < end; e++) {
        const int s = g_esrc[e];
        const float ds = g_dis[s];
        const float4* xs = (const float4*)(x + (size_t)s * 256);
#pragma unroll
        for (int j = 0; j < 2; j++) {
            float4 v = xs[j * 32 + lane];
            acc[j].x += v.x * ds; acc[j].y += v.y * ds;
            acc[j].z += v.z * ds; acc[j].w += v.w * ds;
        }
    }

    float4* xo = (float4*)(xa + (size_t)w * 256);
#pragma unroll
    for (int j = 0; j < 2; j++) {
        acc[j].x *= dd; acc[j].y *= dd; acc[j].z *= dd; acc[j].w *= dd;
        xo[j * 32 + lane] = acc[j];
    }
}

// ---------------------------------------------------------------------------
// Gate: g_gate[i] = sigmoid(dot(x[i], pw) + pb)   (warp per node, F=512)
// ---------------------------------------------------------------------------
__global__ void gate_k(const float* __restrict__ x, const float* __restrict__ pw,
                       const float* __restrict__ pb, int n) {
    int w = (blockIdx.x * blockDim.x + threadIdx.x) >> 5;
    if (w >= n) return;
    int lane = threadIdx.x & 31;
    const float4* row = (const float4*)(x + (size_t)w * 512);
    const float4* p4 = (const float4*)pw;
    float s = 0.f;
#pragma unroll
    for (int j = 0; j < 4; j++) {
        float4 v = row[j * 32 + lane];
        float4 p = p4[j * 32 + lane];
        s += v.x * p.x + v.y * p.y + v.z * p.z + v.w * p.w;
    }
#pragma unroll
    for (int o = 16; o > 0; o >>= 1) s += __shfl_xor_sync(0xffffffffu, s, o);
    if (lane == 0) g_gate[w] = 1.f / (1.f + expf(-(s + pb[0])));
}

// ---------------------------------------------------------------------------
// Segment bounds + pooling
// ---------------------------------------------------------------------------
__global__ void seg_init_k(int n) {
    int g = blockIdx.x * blockDim.x + threadIdx.x;
    if (g < GCNT) { g_start[g] = n; g_end[g] = 0; }
}
__global__ void seg_bounds_k(const int* __restrict__ batch, int n) {
    int i = blockIdx.x * blockDim.x + threadIdx.x;
    if (i >= n) return;
    int g = batch[i];
    atomicMin(&g_start[g], i);
    atomicMax(&g_end[g], i + 1);
}
__global__ void __launch_bounds__(512) pool_k(const float* __restrict__ x) {
    int g = blockIdx.x;
    int s = g_start[g], e = g_end[g];
    int f = threadIdx.x;
    float sum = 0.f, mx = 0.f;
    for (int i = s; i < e; i++) {
        float v = x[(size_t)i * 512 + f];
        sum += v * g_gate[i];
        mx = fmaxf(mx, v);
    }
    g_pool[g * 1024 + f] = sum;
    g_pool[g * 1024 + 512 + f] = mx;  // post-ReLU x >= 0 == empty-segment fill
}

// ---------------------------------------------------------------------------
// Launch
// ---------------------------------------------------------------------------
extern "C" void kernel_launch(void* const* d_in, const int* in_sizes, int n_in,
                              void* d_out, int out_size) {
    const float* xin   = (const float*)d_in[0];
    const int*   ei    = (const int*)d_in[1];
    const int*   batch = (const int*)d_in[2];
    const float* W1 = (const float*)d_in[3];
    const float* b1 = (const float*)d_in[4];
    const float* W2 = (const float*)d_in[5];
    const float* b2 = (const float*)d_in[6];
    const float* W3 = (const float*)d_in[7];
    const float* b3 = (const float*)d_in[8];
    const float* pw = (const float*)d_in[9];
    const float* pb = (const float*)d_in[10];
    const float* Wo = (const float*)d_in[11];
    const float* bo = (const float*)d_in[12];
    float* out = (float*)d_out;

    const int N = in_sizes[0] / 256;
    const int E = in_sizes[1] / 2;
    const int* src = ei;
    const int* dst = ei + E;

    float *p_s, *p_xa, *p_xb, *p_pool, *p_wh, *p_wl;
    cudaGetSymbolAddress((void**)&p_s,  g_s);
    cudaGetSymbolAddress((void**)&p_xa, g_x);
    cudaGetSymbolAddress((void**)&p_xb, g_x2);
    cudaGetSymbolAddress((void**)&p_pool, g_pool);
    cudaGetSymbolAddress((void**)&p_wh, g_wh);
    cudaGetSymbolAddress((void**)&p_wl, g_wl);

    cudaFuncSetAttribute(gemm_mma_k,
                         cudaFuncAttributeMaxDynamicSharedMemorySize, GEMM_SMEM);

    // Weight pre-split (hi/lo tf32)
    wsplit_k<<<(65536 + 255) / 256, 256>>>(W1, 65536, 0);
    wsplit_k<<<(65536 + 255) / 256, 256>>>(W2, 65536, 65536);
    wsplit_k<<<(131072 + 255) / 256, 256>>>(W3, 131072, 131072);
    wsplit_k<<<(2097152 + 255) / 256, 256>>>(Wo, 2097152, 262144);

    // CSR build + normalization
    const int nb = (N + 255) / 256;
    cnt_zero_k<<<nb, 256>>>(N);
    hist_k<<<(E + 255) / 256, 256>>>(dst, E);
    dis_k<<<nb, 256>>>(N);
    scan1_k<<<nb, 256>>>(N);
    scan2_k<<<1, 256>>>(nb, N);
    scan3_k<<<nb, 256>>>(N);
    scatter_k<<<(E + 255) / 256, 256>>>(src, dst, E);

    // --- GCN layers: aggregate (256f) then GEMM (bias+relu fused) ---
    struct { int woff; const float* b; int fout; } L[3] = {
        {0, b1, 256}, {65536, b2, 256}, {131072, b3, 512}};
    const float* cur = xin;
    float* act[2] = {p_xa, p_xb};
    float* x_out = nullptr;
    const int aggblocks = (N * 32 + 255) / 256;
    for (int l = 0; l < 3; l++) {
        x_out = act[l & 1];
        agg_pre_k<<<aggblocks, 256>>>(cur, p_s, N);
        dim3 grid(L[l].fout / 128, (N + 127) / 128);
        gemm_mma_k<<<grid, 256, GEMM_SMEM>>>(p_s, p_wh + L[l].woff,
                                             p_wl + L[l].woff, x_out,
                                             N, L[l].fout, 256, L[l].b);
        cur = x_out;
    }

    // --- Pooling ---
    gate_k<<<aggblocks, 256>>>(x_out, pw, pb, N);
    seg_init_k<<<(GCNT + 255) / 256, 256>>>(N);
    seg_bounds_k<<<nb, 256>>>(batch, N);
    pool_k<<<GCNT, 512>>>(x_out);

    // --- Head: relu(pool @ Wo + bo) ---
    dim3 hgrid(FPOUT / 128, (GCNT + 127) / 128);
    gemm_mma_k<<<hgrid, 256, GEMM_SMEM>>>(p_pool, p_wh + 262144, p_wl + 262144,
                                          out, GCNT, FPOUT, 1024, bo);
}

// round 17
// speedup vs baseline: 1.8285x; 1.4210x over previous
#include <cuda_runtime.h>
#include <cuda_bf16.h>
#include <math.h>
#include <stdint.h>

// Fixed problem shapes
#define NMAX   50000
#define EMAX   800000
#define FMAX   512
#define GCNT   512
#define FPOUT  2048
#define WPACK  1179648   // packed words: W1 32768 + W2 32768 + W3 65536 + Wo 1048576

// Scratch (device globals: no allocation allowed)
__device__ uint32_t g_s_hi[(size_t)NMAX * 128];  // aggregated input, bf16-pair hi
__device__ uint32_t g_s_lo[(size_t)NMAX * 128];  // aggregated input, bf16-pair lo
__device__ float    g_x [(size_t)NMAX * FMAX];   // activation ping (fp32)
__device__ float    g_x2[(size_t)NMAX * FMAX];   // activation pong (fp32)
__device__ uint32_t g_wh[WPACK];                 // weights, bf16-pair hi [K/2][N]
__device__ uint32_t g_wl[WPACK];                 // weights, bf16-pair lo
__device__ uint32_t g_ph[512 * 512];             // head A (pool) hi
__device__ uint32_t g_pl[512 * 512];             // head A (pool) lo
__device__ float    g_dis[NMAX];
__device__ float    g_gate[NMAX];
__device__ float    g_pool[GCNT * 1024];
__device__ int      g_cnt[NMAX];
__device__ int      g_rowptr[NMAX + 1];
__device__ int      g_fill[NMAX];
__device__ int      g_esrc[EMAX];
__device__ int      g_bsum[256];
__device__ int      g_start[GCNT];
__device__ int      g_end[GCNT];

__device__ __forceinline__ uint32_t smem_u32(const void* p) {
    uint32_t a;
    asm("{ .reg .u64 t; cvta.to.shared.u64 t, %1; cvt.u32.u64 %0, t; }"
        : "=r"(a) : "l"(p));
    return a;
}
__device__ __forceinline__ void cp16(uint32_t dst, const void* src, int srcbytes) {
    asm volatile("cp.async.cg.shared.global [%0], [%1], 16, %2;"
                 :: "r"(dst), "l"(src), "r"(srcbytes) : "memory");
}
#define CP_COMMIT() asm volatile("cp.async.commit_group;" ::: "memory")
#define CP_WAIT1()  asm volatile("cp.async.wait_group 1;" ::: "memory")
#define CP_WAIT0()  asm volatile("cp.async.wait_group 0;" ::: "memory")

__device__ __forceinline__ void mma_bf16(float* c, const uint32_t* a,
                                         uint32_t b0, uint32_t b1) {
    asm volatile(
        "mma.sync.aligned.m16n8k16.row.col.f32.bf16.bf16.f32 "
        "{%0,%1,%2,%3}, {%4,%5,%6,%7}, {%8,%9}, {%0,%1,%2,%3};"
        : "+f"(c[0]), "+f"(c[1]), "+f"(c[2]), "+f"(c[3])
        : "r"(a[0]), "r"(a[1]), "r"(a[2]), "r"(a[3]), "r"(b0), "r"(b1));
}

// pack two floats -> bf16x2 word (lower half = first/even-k element)
__device__ __forceinline__ uint32_t pk(float a, float b) {
    __nv_bfloat162 t = __floats2bfloat162_rn(a, b);
    return *(uint32_t*)&t;
}
// split helpers
__device__ __forceinline__ void split2(float a, float b, uint32_t& hi, uint32_t& lo) {
    float ha = __bfloat162float(__float2bfloat16_rn(a));
    float hb = __bfloat162float(__float2bfloat16_rn(b));
    hi = pk(ha, hb);
    lo = pk(a - ha, b - hb);
}

// ===========================================================================
// GEMM via mma.sync m16n8k16 bf16 split-precision, cp.async 2-stage pipeline.
//   C[row] = relu((A@B)[row] + bias[col])
// A pre-split+pair-packed (AH/AL uint32 [M][K/2]); B pre-split+packed
// (WH/WL uint32 [K/2][N]). CTA 128x128, K-chunk 32 (2 k16 steps), 8 warps,
// warp tile 32x64; 3 MMAs per atom (hh + lh + hl).
// ===========================================================================
#define CHK  32
#define PAW  20      // A smem pitch (words): banks (20q+s) all distinct
#define PBW  136     // B smem pitch (words): banks (8s+q) all distinct
#define SZ_A (128 * PAW * 4)             // 10240 B
#define SZ_B (16 * PBW * 4)              // 8704 B
#define STAGE (2 * SZ_A + 2 * SZ_B)      // 37888 B
#define OFF_AH(st) ((st) * STAGE)
#define OFF_AL(st) ((st) * STAGE + SZ_A)
#define OFF_BH(st) ((st) * STAGE + 2 * SZ_A)
#define OFF_BL(st) ((st) * STAGE + 2 * SZ_A + SZ_B)
#define GEMM_SMEM (2 * STAGE)            // 75776 B

__global__ void __launch_bounds__(256, 2) gemm_bf16_k(
    const uint32_t* __restrict__ AHg, const uint32_t* __restrict__ ALg,
    const uint32_t* __restrict__ WHp, const uint32_t* __restrict__ WLp,
    float* __restrict__ C, int M, int Nout, int K,
    const float* __restrict__ bias)
{
    extern __shared__ char smem[];
    const uint32_t sb = smem_u32(smem);

    const int tid  = threadIdx.x;
    const int lane = tid & 31;
    const int wid  = tid >> 5;
    const int bm = blockIdx.y * 128;
    const int bn = blockIdx.x * 128;
    const int wm = (wid & 3) * 32;
    const int wn = (wid >> 2) * 64;
    const int q = lane >> 2;
    const int s = lane & 3;

    const int K2 = K >> 1;           // words per A row
    const int nchunk = K / CHK;

    float acc[2][8][4];
#pragma unroll
    for (int i = 0; i < 2; i++)
#pragma unroll
        for (int j = 0; j < 8; j++)
#pragma unroll
            for (int v = 0; v < 4; v++) acc[i][j][v] = 0.f;

    auto prefetch = [&](int ch) {
        const int st = ch & 1;
#pragma unroll
        for (int r = 0; r < 2; r++) {
            const int c = tid + r * 256;
            // A: 128 rows x 16 words per stage; 16B-chunk = 4 words
            {
                const int row = c >> 2, off = c & 3;
                const int grow = bm + row;
                const size_t so = (size_t)grow * K2 + ch * 16 + off * 4;
                const int nb = (grow < M) ? 16 : 0;
                cp16(sb + OFF_AH(st) + row * (PAW * 4) + off * 16, AHg + so, nb);
                cp16(sb + OFF_AL(st) + row * (PAW * 4) + off * 16, ALg + so, nb);
            }
            // B: 16 kp-rows x 128 words
            {
                const int kr = c >> 5, off = c & 31;
                const size_t so = (size_t)(ch * 16 + kr) * Nout + bn + off * 4;
                cp16(sb + OFF_BH(st) + kr * (PBW * 4) + off * 16, WHp + so, 16);
                cp16(sb + OFF_BL(st) + kr * (PBW * 4) + off * 16, WLp + so, 16);
            }
        }
        CP_COMMIT();
    };

    prefetch(0);
    if (nchunk > 1) prefetch(1);

    for (int ch = 0; ch < nchunk; ch++) {
        const int buf = ch & 1;
        if (ch + 1 < nchunk) { CP_WAIT1(); } else { CP_WAIT0(); }
        __syncthreads();

        const uint32_t* AH = (const uint32_t*)(smem + OFF_AH(buf));
        const uint32_t* AL = (const uint32_t*)(smem + OFF_AL(buf));
        const uint32_t* BH = (const uint32_t*)(smem + OFF_BH(buf));
        const uint32_t* BL = (const uint32_t*)(smem + OFF_BL(buf));

#pragma unroll
        for (int kk = 0; kk < 2; kk++) {
            const int kb = kk * 8;
            uint32_t ah[2][4], al[2][4];
#pragma unroll
            for (int am = 0; am < 2; am++) {
                const int r0 = wm + am * 16 + q;
                ah[am][0] = AH[r0 * PAW + kb + s];
                ah[am][1] = AH[(r0 + 8) * PAW + kb + s];
                ah[am][2] = AH[r0 * PAW + kb + s + 4];
                ah[am][3] = AH[(r0 + 8) * PAW + kb + s + 4];
                al[am][0] = AL[r0 * PAW + kb + s];
                al[am][1] = AL[(r0 + 8) * PAW + kb + s];
                al[am][2] = AL[r0 * PAW + kb + s + 4];
                al[am][3] = AL[(r0 + 8) * PAW + kb + s + 4];
            }
#pragma unroll
            for (int an = 0; an < 8; an++) {
                const int n0 = wn + an * 8 + q;
                const uint32_t bh0 = BH[(kb + s) * PBW + n0];
                const uint32_t bh1 = BH[(kb + s + 4) * PBW + n0];
                const uint32_t bl0 = BL[(kb + s) * PBW + n0];
                const uint32_t bl1 = BL[(kb + s + 4) * PBW + n0];
#pragma unroll
                for (int am = 0; am < 2; am++) {
                    mma_bf16(acc[am][an], ah[am], bh0, bh1);
                    mma_bf16(acc[am][an], al[am], bh0, bh1);
                    mma_bf16(acc[am][an], ah[am], bl0, bl1);
                }
            }
        }
        __syncthreads();
        if (ch + 2 < nchunk) prefetch(ch + 2);
    }

    // ---- epilogue: C = relu(acc + bias) ----
#pragma unroll
    for (int am = 0; am < 2; am++) {
        const int row0 = bm + wm + am * 16 + q;
        const int row1 = row0 + 8;
#pragma unroll
        for (int an = 0; an < 8; an++) {
            const int col = bn + wn + an * 8 + s * 2;
            const float bx = bias[col], by = bias[col + 1];
            if (row0 < M) {
                float2 o = make_float2(fmaxf(acc[am][an][0] + bx, 0.f),
                                       fmaxf(acc[am][an][1] + by, 0.f));
                *(float2*)(C + (size_t)row0 * Nout + col) = o;
            }
            if (row1 < M) {
                float2 o = make_float2(fmaxf(acc[am][an][2] + bx, 0.f),
                                       fmaxf(acc[am][an][3] + by, 0.f));
                *(float2*)(C + (size_t)row1 * Nout + col) = o;
            }
        }
    }
}

// ---------------------------------------------------------------------------
// Weight pre-split + pair-pack: word(kp,n): lo-half = bf16(W[2kp][n]),
// hi-half = bf16(W[2kp+1][n]); residuals to g_wl.
// ---------------------------------------------------------------------------
__global__ void wsplit_k(const float* __restrict__ W, int K2, int N, int dstoff) {
    int i = blockIdx.x * blockDim.x + threadIdx.x;
    if (i >= K2 * N) return;
    int kp = i / N, n = i - kp * N;
    float w0 = W[(size_t)(2 * kp) * N + n];
    float w1 = W[(size_t)(2 * kp + 1) * N + n];
    uint32_t hi, lo;
    split2(w0, w1, hi, lo);
    g_wh[dstoff + i] = hi;
    g_wl[dstoff + i] = lo;
}

// Flat fp32 -> bf16-split pair pack (for pool output; row length even)
__global__ void pack_flat_k(const float* __restrict__ src,
                            uint32_t* __restrict__ hi_out,
                            uint32_t* __restrict__ lo_out, int nwords) {
    int i = blockIdx.x * blockDim.x + threadIdx.x;
    if (i >= nwords) return;
    float2 v = *(const float2*)(src + 2 * i);
    uint32_t hi, lo;
    split2(v.x, v.y, hi, lo);
    hi_out[i] = hi;
    lo_out[i] = lo;
}

// ---------------------------------------------------------------------------
// CSR build: histogram -> 3-pass parallel scan -> cursor scatter
// ---------------------------------------------------------------------------
__global__ void cnt_zero_k(int n) {
    int i = blockIdx.x * blockDim.x + threadIdx.x;
    if (i < n) g_cnt[i] = 0;
}
__global__ void hist_k(const int* __restrict__ dst, int e) {
    int i = blockIdx.x * blockDim.x + threadIdx.x;
    if (i < e) atomicAdd(&g_cnt[dst[i]], 1);
}
__global__ void dis_k(int n) {
    int i = blockIdx.x * blockDim.x + threadIdx.x;
    if (i < n) g_dis[i] = rsqrtf((float)(g_cnt[i] + 1));  // +1 self-loop
}
__global__ void scan1_k(int n) {
    __shared__ int sh[256];
    int i = blockIdx.x * 256 + threadIdx.x;
    sh[threadIdx.x] = (i < n) ? g_cnt[i] : 0;
    __syncthreads();
    for (int o = 128; o > 0; o >>= 1) {
        if (threadIdx.x < o) sh[threadIdx.x] += sh[threadIdx.x + o];
        __syncthreads();
    }
    if (threadIdx.x == 0) g_bsum[blockIdx.x] = sh[0];
}
__global__ void scan2_k(int nb, int n) {
    __shared__ int sh[256];
    int t = threadIdx.x;
    int v = (t < nb) ? g_bsum[t] : 0;
    sh[t] = v; __syncthreads();
    for (int o = 1; o < 256; o <<= 1) {
        int u = (t >= o) ? sh[t - o] : 0;
        __syncthreads();
        sh[t] += u;
        __syncthreads();
    }
    if (t < nb) g_bsum[t] = sh[t] - v;  // exclusive
    if (t == 255) g_rowptr[n] = sh[255];
}
__global__ void scan3_k(int n) {
    __shared__ int sh[256];
    int t = threadIdx.x;
    int i = blockIdx.x * 256 + t;
    int v = (i < n) ? g_cnt[i] : 0;
    sh[t] = v; __syncthreads();
    for (int o = 1; o < 256; o <<= 1) {
        int u = (t >= o) ? sh[t - o] : 0;
        __syncthreads();
        sh[t] += u;
        __syncthreads();
    }
    if (i < n) {
        int off = g_bsum[blockIdx.x] + sh[t] - v;
        g_rowptr[i] = off;
        g_fill[i] = off;
    }
}
__global__ void scatter_k(const int* __restrict__ src, const int* __restrict__ dst,
                          int e) {
    int i = blockIdx.x * blockDim.x + threadIdx.x;
    if (i >= e) return;
    int pos = atomicAdd(&g_fill[dst[i]], 1);
    g_esrc[pos] = src[i];
}

// ---------------------------------------------------------------------------
// Pre-GEMM pull-aggregation (warp per node, 256 features):
//   agg = dis[d] * (dis[d]*x[d] + sum_{s in in(d)} dis[s]*x[s])
// Output written directly as bf16-split pair-packed (GEMM A format).
// ---------------------------------------------------------------------------
__global__ void __launch_bounds__(256) agg_pre_k(
    const float* __restrict__ x, uint32_t* __restrict__ oh,
    uint32_t* __restrict__ ol, int n)
{
    int w = (blockIdx.x * blockDim.x + threadIdx.x) >> 5;
    if (w >= n) return;
    const int lane = threadIdx.x & 31;

    const float dd = g_dis[w];
    float4 acc[2];
    const float4* xr = (const float4*)(x + (size_t)w * 256);
#pragma unroll
    for (int j = 0; j < 2; j++) {
        float4 v = xr[j * 32 + lane];
        acc[j].x = v.x * dd; acc[j].y = v.y * dd;
        acc[j].z = v.z * dd; acc[j].w = v.w * dd;
    }

    const int beg = g_rowptr[w], end = g_rowptr[w + 1];
    for (int e = beg; e < end; e++) {
        const int s = g_esrc[e];
        const float ds = g_dis[s];
        const float4* xs = (const float4*)(x + (size_t)s * 256);
#pragma unroll
        for (int j = 0; j < 2; j++) {
            float4 v = xs[j * 32 + lane];
            acc[j].x += v.x * ds; acc[j].y += v.y * ds;
            acc[j].z += v.z * ds; acc[j].w += v.w * ds;
        }
    }

#pragma unroll
    for (int j = 0; j < 2; j++) {
        acc[j].x *= dd; acc[j].y *= dd; acc[j].z *= dd; acc[j].w *= dd;
        uint32_t h0, l0, h1, l1;
        split2(acc[j].x, acc[j].y, h0, l0);
        split2(acc[j].z, acc[j].w, h1, l1);
        const size_t idx = (size_t)w * 128 + j * 64 + lane * 2;
        *(uint2*)(oh + idx) = make_uint2(h0, h1);
        *(uint2*)(ol + idx) = make_uint2(l0, l1);
    }
}

// ---------------------------------------------------------------------------
// Gate: g_gate[i] = sigmoid(dot(x[i], pw) + pb)   (warp per node, F=512)
// ---------------------------------------------------------------------------
__global__ void gate_k(const float* __restrict__ x, const float* __restrict__ pw,
                       const float* __restrict__ pb, int n) {
    int w = (blockIdx.x * blockDim.x + threadIdx.x) >> 5;
    if (w >= n) return;
    int lane = threadIdx.x & 31;
    const float4* row = (const float4*)(x + (size_t)w * 512);
    const float4* p4 = (const float4*)pw;
    float s = 0.f;
#pragma unroll
    for (int j = 0; j < 4; j++) {
        float4 v = row[j * 32 + lane];
        float4 p = p4[j * 32 + lane];
        s += v.x * p.x + v.y * p.y + v.z * p.z + v.w * p.w;
    }
#pragma unroll
    for (int o = 16; o > 0; o >>= 1) s += __shfl_xor_sync(0xffffffffu, s, o);
    if (lane == 0) g_gate[w] = 1.f / (1.f + expf(-(s + pb[0])));
}

// ---------------------------------------------------------------------------
// Segment bounds + pooling
// ---------------------------------------------------------------------------
__global__ void seg_init_k(int n) {
    int g = blockIdx.x * blockDim.x + threadIdx.x;
    if (g < GCNT) { g_start[g] = n; g_end[g] = 0; }
}
__global__ void seg_bounds_k(const int* __restrict__ batch, int n) {
    int i = blockIdx.x * blockDim.x + threadIdx.x;
    if (i >= n) return;
    int g = batch[i];
    atomicMin(&g_start[g], i);
    atomicMax(&g_end[g], i + 1);
}
__global__ void __launch_bounds__(512) pool_k(const float* __restrict__ x) {
    int g = blockIdx.x;
    int s = g_start[g], e = g_end[g];
    int f = threadIdx.x;
    float sum = 0.f, mx = 0.f;
    for (int i = s; i < e; i++) {
        float v = x[(size_t)i * 512 + f];
        sum += v * g_gate[i];
        mx = fmaxf(mx, v);
    }
    g_pool[g * 1024 + f] = sum;
    g_pool[g * 1024 + 512 + f] = mx;  // post-ReLU x >= 0 == empty-segment fill
}

// ---------------------------------------------------------------------------
// Launch
// ---------------------------------------------------------------------------
extern "C" void kernel_launch(void* const* d_in, const int* in_sizes, int n_in,
                              void* d_out, int out_size) {
    const float* xin   = (const float*)d_in[0];
    const int*   ei    = (const int*)d_in[1];
    const int*   batch = (const int*)d_in[2];
    const float* W1 = (const float*)d_in[3];
    const float* b1 = (const float*)d_in[4];
    const float* W2 = (const float*)d_in[5];
    const float* b2 = (const float*)d_in[6];
    const float* W3 = (const float*)d_in[7];
    const float* b3 = (const float*)d_in[8];
    const float* pw = (const float*)d_in[9];
    const float* pb = (const float*)d_in[10];
    const float* Wo = (const float*)d_in[11];
    const float* bo = (const float*)d_in[12];
    float* out = (float*)d_out;

    const int N = in_sizes[0] / 256;
    const int E = in_sizes[1] / 2;
    const int* src = ei;
    const int* dst = ei + E;

    float *p_xa, *p_xb, *p_pool;
    uint32_t *p_sh, *p_sl, *p_wh, *p_wl, *p_ph, *p_pl;
    cudaGetSymbolAddress((void**)&p_xa, g_x);
    cudaGetSymbolAddress((void**)&p_xb, g_x2);
    cudaGetSymbolAddress((void**)&p_pool, g_pool);
    cudaGetSymbolAddress((void**)&p_sh, g_s_hi);
    cudaGetSymbolAddress((void**)&p_sl, g_s_lo);
    cudaGetSymbolAddress((void**)&p_wh, g_wh);
    cudaGetSymbolAddress((void**)&p_wl, g_wl);
    cudaGetSymbolAddress((void**)&p_ph, g_ph);
    cudaGetSymbolAddress((void**)&p_pl, g_pl);

    cudaFuncSetAttribute(gemm_bf16_k,
                         cudaFuncAttributeMaxDynamicSharedMemorySize, GEMM_SMEM);

    // Weight pre-split + pack (word offsets)
    wsplit_k<<<(32768 + 255) / 256, 256>>>(W1, 128, 256, 0);
    wsplit_k<<<(32768 + 255) / 256, 256>>>(W2, 128, 256, 32768);
    wsplit_k<<<(65536 + 255) / 256, 256>>>(W3, 128, 512, 65536);
    wsplit_k<<<(1048576 + 255) / 256, 256>>>(Wo, 512, 2048, 131072);

    // CSR build + normalization
    const int nb = (N + 255) / 256;
    cnt_zero_k<<<nb, 256>>>(N);
    hist_k<<<(E + 255) / 256, 256>>>(dst, E);
    dis_k<<<nb, 256>>>(N);
    scan1_k<<<nb, 256>>>(N);
    scan2_k<<<1, 256>>>(nb, N);
    scan3_k<<<nb, 256>>>(N);
    scatter_k<<<(E + 255) / 256, 256>>>(src, dst, E);

    // --- GCN layers: aggregate+pack (256f) then bf16-split GEMM ---
    struct { int woff; const float* b; int fout; } L[3] = {
        {0, b1, 256}, {32768, b2, 256}, {65536, b3, 512}};
    const float* cur = xin;
    float* act[2] = {p_xa, p_xb};
    float* x_out = nullptr;
    const int aggblocks = (N * 32 + 255) / 256;
    for (int l = 0; l < 3; l++) {
        x_out = act[l & 1];
        agg_pre_k<<<aggblocks, 256>>>(cur, p_sh, p_sl, N);
        dim3 grid(L[l].fout / 128, (N + 127) / 128);
        gemm_bf16_k<<<grid, 256, GEMM_SMEM>>>(p_sh, p_sl,
                                              p_wh + L[l].woff, p_wl + L[l].woff,
                                              x_out, N, L[l].fout, 256, L[l].b);
        cur = x_out;
    }

    // --- Pooling ---
    gate_k<<<aggblocks, 256>>>(x_out, pw, pb, N);
    seg_init_k<<<(GCNT + 255) / 256, 256>>>(N);
    seg_bounds_k<<<nb, 256>>>(batch, N);
    pool_k<<<GCNT, 512>>>(x_out);

    // --- Head: pack pool then relu(pool @ Wo + bo) ---
    pack_flat_k<<<(262144 + 255) / 256, 256>>>(p_pool, p_ph, p_pl, 262144);
    dim3 hgrid(FPOUT / 128, (GCNT + 127) / 128);
    gemm_bf16_k<<<hgrid, 256, GEMM_SMEM>>>(p_ph, p_pl, p_wh + 131072,
                                           p_wl + 131072, out, GCNT, FPOUT,
                                           1024, bo);
}